// round 1
// baseline (speedup 1.0000x reference)
#include <cuda_runtime.h>

// Problem dims (fixed by the dataset)
#define BB 8
#define TT 256
#define UU 64
#define ENC_DIM 512
#define PRED_DIM 640
#define JDIM 512
#define VOCAB 1024

// Scratch for projections (allowed: __device__ globals, no runtime alloc)
__device__ float g_enc_p[BB * TT * JDIM];    // 4 MB
__device__ float g_pred_p[BB * UU * JDIM];   // 1 MB

// Accurate-enough tanh independent of fast-math flags:
// tanh(x) = sign(x) * (1 - e) / (1 + e), e = exp(-2|x|)  (stable, no overflow)
__device__ __forceinline__ float tanh_f(float x) {
    float ax = fabsf(x);
    float e  = __expf(-2.0f * ax);
    float t  = (1.0f - e) / (1.0f + e);
    return (x < 0.0f) ? -t : t;
}

// ---------------------------------------------------------------------------
// Projection GEMM: C[M, 512] = A[M, K] @ W[K, 512] + bias
// BM=64, BN=128, BK=16, 256 threads, 4x8 microtile.
// WHICH = 0 -> writes g_enc_p, WHICH = 1 -> writes g_pred_p
// ---------------------------------------------------------------------------
template <int K, int WHICH>
__global__ __launch_bounds__(256) void proj_kernel(
    const float* __restrict__ A,
    const float* __restrict__ W,
    const float* __restrict__ bias)
{
    __shared__ float As[16][68];   // [k][m], padded (stride 68 floats)
    __shared__ float Bs[16][128];  // [k][n]

    float* __restrict__ C = (WHICH == 0) ? g_enc_p : g_pred_p;
    const int N = JDIM;

    const int tid = threadIdx.x;
    const int ty  = tid >> 4;       // 0..15 -> m group
    const int tx  = tid & 15;       // 0..15 -> n lane
    const int m0  = blockIdx.y * 64;
    const int n0  = blockIdx.x * 128;

    const int lm = tid >> 2;          // 0..63 : A row within tile
    const int lk = (tid & 3) << 2;    // 0,4,8,12 : k offset (float4)

    float acc[4][8];
#pragma unroll
    for (int i = 0; i < 4; i++)
#pragma unroll
        for (int j = 0; j < 8; j++) acc[i][j] = 0.0f;

    for (int k0 = 0; k0 < K; k0 += 16) {
        // A tile: 64x16, float4 per thread
        float4 a4 = *(const float4*)&A[(m0 + lm) * K + k0 + lk];
        As[lk + 0][lm] = a4.x;
        As[lk + 1][lm] = a4.y;
        As[lk + 2][lm] = a4.z;
        As[lk + 3][lm] = a4.w;

        // B tile: 16x128, 2 x float4 per thread
#pragma unroll
        for (int r = 0; r < 2; r++) {
            int f  = tid + r * 256;
            int kk = f >> 5;
            int nn = (f & 31) << 2;
            *(float4*)&Bs[kk][nn] = *(const float4*)&W[(k0 + kk) * N + n0 + nn];
        }
        __syncthreads();

#pragma unroll
        for (int k = 0; k < 16; k++) {
            float4 av = *(const float4*)&As[k][ty << 2];
            float a[4] = {av.x, av.y, av.z, av.w};
            float bb[8];
#pragma unroll
            for (int j = 0; j < 8; j++) bb[j] = Bs[k][tx + (j << 4)];
#pragma unroll
            for (int i = 0; i < 4; i++)
#pragma unroll
                for (int j = 0; j < 8; j++)
                    acc[i][j] = fmaf(a[i], bb[j], acc[i][j]);
        }
        __syncthreads();
    }

#pragma unroll
    for (int j = 0; j < 8; j++) {
        float bj = bias[n0 + tx + (j << 4)];
#pragma unroll
        for (int i = 0; i < 4; i++)
            C[(m0 + (ty << 2) + i) * N + n0 + tx + (j << 4)] = acc[i][j] + bj;
    }
}

// ---------------------------------------------------------------------------
// Fused joint GEMM:
//   out[bt, u, v] = sum_k tanh(enc_p[bt,k] + pred_p[b,u,k]) * W_joint[k,v] + b_joint[v]
// Block = one bt (all 64 u rows) x 128 vocab cols. BK=16.
// tanh is fused into the A-tile load (recomputed VOCAB/128 = 8x, cheap MUFU).
// ---------------------------------------------------------------------------
__global__ __launch_bounds__(256) void joint_kernel(
    const float* __restrict__ W,     // [JDIM, VOCAB]
    const float* __restrict__ bias,  // [VOCAB]
    float* __restrict__ out)         // [BB*TT, UU, VOCAB]
{
    __shared__ float As[16][68];
    __shared__ float Bs[16][128];

    const int tid = threadIdx.x;
    const int ty  = tid >> 4;
    const int tx  = tid & 15;
    const int bt  = blockIdx.y;          // 0..2047
    const int b   = bt >> 8;             // batch index
    const int n0  = blockIdx.x * 128;

    const float* __restrict__ encrow = g_enc_p + (size_t)bt * JDIM;
    const float* __restrict__ predb  = g_pred_p + (size_t)b * UU * JDIM;

    const int lm = tid >> 2;           // u row within tile (0..63)
    const int lk = (tid & 3) << 2;     // k offset

    float acc[4][8];
#pragma unroll
    for (int i = 0; i < 4; i++)
#pragma unroll
        for (int j = 0; j < 8; j++) acc[i][j] = 0.0f;

    for (int k0 = 0; k0 < JDIM; k0 += 16) {
        // A tile with fused broadcast-add + tanh
        float4 p4 = *(const float4*)&predb[lm * JDIM + k0 + lk];
        float4 e4 = *(const float4*)&encrow[k0 + lk];
        As[lk + 0][lm] = tanh_f(p4.x + e4.x);
        As[lk + 1][lm] = tanh_f(p4.y + e4.y);
        As[lk + 2][lm] = tanh_f(p4.z + e4.z);
        As[lk + 3][lm] = tanh_f(p4.w + e4.w);

        // B tile 16x128 from W_joint
#pragma unroll
        for (int r = 0; r < 2; r++) {
            int f  = tid + r * 256;
            int kk = f >> 5;
            int nn = (f & 31) << 2;
            *(float4*)&Bs[kk][nn] = *(const float4*)&W[(k0 + kk) * VOCAB + n0 + nn];
        }
        __syncthreads();

#pragma unroll
        for (int k = 0; k < 16; k++) {
            float4 av = *(const float4*)&As[k][ty << 2];
            float a[4] = {av.x, av.y, av.z, av.w};
            float bb[8];
#pragma unroll
            for (int j = 0; j < 8; j++) bb[j] = Bs[k][tx + (j << 4)];
#pragma unroll
            for (int i = 0; i < 4; i++)
#pragma unroll
                for (int j = 0; j < 8; j++)
                    acc[i][j] = fmaf(a[i], bb[j], acc[i][j]);
        }
        __syncthreads();
    }

    // Epilogue: add b_joint, store
    const size_t rowbase = (size_t)bt * UU * VOCAB;
#pragma unroll
    for (int j = 0; j < 8; j++) {
        float bj = bias[n0 + tx + (j << 4)];
#pragma unroll
        for (int i = 0; i < 4; i++) {
            int u = (ty << 2) + i;
            out[rowbase + (size_t)u * VOCAB + n0 + tx + (j << 4)] = acc[i][j] + bj;
        }
    }
}

extern "C" void kernel_launch(void* const* d_in, const int* in_sizes, int n_in,
                              void* d_out, int out_size)
{
    const float* enc_out = (const float*)d_in[0];  // (8,256,512)
    const float* pred_out = (const float*)d_in[1]; // (8,64,640)
    const float* W_enc   = (const float*)d_in[2];  // (512,512)
    const float* b_enc   = (const float*)d_in[3];  // (512,)
    const float* W_pred  = (const float*)d_in[4];  // (640,512)
    const float* b_pred  = (const float*)d_in[5];  // (512,)
    const float* W_joint = (const float*)d_in[6];  // (512,1024)
    const float* b_joint = (const float*)d_in[7];  // (1024,)
    float* out = (float*)d_out;                    // (8,256,64,1024)

    // enc projection: M = 8*256 = 2048, K = 512, N = 512
    {
        dim3 grid(JDIM / 128, (BB * TT) / 64);
        proj_kernel<ENC_DIM, 0><<<grid, 256>>>(enc_out, W_enc, b_enc);
    }
    // pred projection: M = 8*64 = 512, K = 640, N = 512
    {
        dim3 grid(JDIM / 128, (BB * UU) / 64);
        proj_kernel<PRED_DIM, 1><<<grid, 256>>>(pred_out, W_pred, b_pred);
    }
    // fused joint: grid = (1024/128 vocab tiles, 2048 bt)
    {
        dim3 grid(VOCAB / 128, BB * TT);
        joint_kernel<<<grid, 256>>>(W_joint, b_joint, out);
    }
}

// round 3
// speedup vs baseline: 2.7500x; 2.7500x over previous
#include <cuda_runtime.h>
#include <cuda_bf16.h>
#include <cstdint>

#define BB 8
#define TT 256
#define UU 64
#define ENC_DIM 512
#define PRED_DIM 640
#define JDIM 512
#define VOCAB 1024
#define MROWS (BB * TT * UU)   // 131072

// ---------------------------------------------------------------------------
// Device scratch
// ---------------------------------------------------------------------------
__device__ float g_enc_p[BB * TT * JDIM];                 // 4 MB
__device__ float g_pred_p[BB * UU * JDIM];                // 1 MB
__device__ __nv_bfloat16 g_a_hi[(size_t)MROWS * JDIM];    // 128 MB
__device__ __nv_bfloat16 g_a_lo[(size_t)MROWS * JDIM];    // 128 MB
__device__ __nv_bfloat16 g_wt_hi[VOCAB * JDIM];           // 1 MB
__device__ __nv_bfloat16 g_wt_lo[VOCAB * JDIM];           // 1 MB

// ---------------------------------------------------------------------------
// Helpers
// ---------------------------------------------------------------------------
__device__ __forceinline__ uint32_t smem_u32(const void* p) {
    uint32_t a;
    asm("{ .reg .u64 t; cvta.to.shared.u64 t, %1; cvt.u32.u64 %0, t; }" : "=r"(a) : "l"(p));
    return a;
}
#define CP16(dst, src) \
    asm volatile("cp.async.cg.shared.global [%0], [%1], 16;" :: "r"((uint32_t)(dst)), "l"(src) : "memory")
#define CP_COMMIT() asm volatile("cp.async.commit_group;" ::: "memory")

#define LDSM4(r, addr) \
    asm volatile("ldmatrix.sync.aligned.m8n8.x4.shared.b16 {%0,%1,%2,%3}, [%4];" \
                 : "=r"((r)[0]), "=r"((r)[1]), "=r"((r)[2]), "=r"((r)[3]) : "r"(addr))

#define MMA16816(acc, a, b0, b1) \
    asm volatile("mma.sync.aligned.m16n8k16.row.col.f32.bf16.bf16.f32 " \
                 "{%0,%1,%2,%3},{%4,%5,%6,%7},{%8,%9},{%0,%1,%2,%3};" \
                 : "+f"((acc)[0]), "+f"((acc)[1]), "+f"((acc)[2]), "+f"((acc)[3]) \
                 : "r"((a)[0]), "r"((a)[1]), "r"((a)[2]), "r"((a)[3]), "r"(b0), "r"(b1))

// Accurate tanh (independent of fast-math): sign(x)*(1-e)/(1+e), e = exp(-2|x|)
__device__ __forceinline__ float tanh_f(float x) {
    float ax = fabsf(x);
    float e  = __expf(-2.0f * ax);
    float t  = (1.0f - e) / (1.0f + e);
    return (x < 0.0f) ? -t : t;
}
__device__ __forceinline__ uint32_t pack2(__nv_bfloat16 a, __nv_bfloat16 b) {
    return (uint32_t)__bfloat16_as_ushort(a) | ((uint32_t)__bfloat16_as_ushort(b) << 16);
}

// ---------------------------------------------------------------------------
// Projection GEMM (fp32 SIMT): C[M, 512] = A[M, K] @ W[K, 512] + bias
// ---------------------------------------------------------------------------
template <int K, int WHICH>
__global__ __launch_bounds__(256) void proj_kernel(
    const float* __restrict__ A, const float* __restrict__ W, const float* __restrict__ bias)
{
    __shared__ float As[16][68];
    __shared__ float Bs[16][128];
    float* __restrict__ C = (WHICH == 0) ? g_enc_p : g_pred_p;
    const int N = JDIM;
    const int tid = threadIdx.x;
    const int ty = tid >> 4, tx = tid & 15;
    const int m0 = blockIdx.y * 64, n0 = blockIdx.x * 128;
    const int lm = tid >> 2, lk = (tid & 3) << 2;

    float acc[4][8];
#pragma unroll
    for (int i = 0; i < 4; i++)
#pragma unroll
        for (int j = 0; j < 8; j++) acc[i][j] = 0.0f;

    for (int k0 = 0; k0 < K; k0 += 16) {
        float4 a4 = *(const float4*)&A[(m0 + lm) * K + k0 + lk];
        As[lk + 0][lm] = a4.x; As[lk + 1][lm] = a4.y;
        As[lk + 2][lm] = a4.z; As[lk + 3][lm] = a4.w;
#pragma unroll
        for (int r = 0; r < 2; r++) {
            int f = tid + r * 256;
            int kk = f >> 5, nn = (f & 31) << 2;
            *(float4*)&Bs[kk][nn] = *(const float4*)&W[(k0 + kk) * N + n0 + nn];
        }
        __syncthreads();
#pragma unroll
        for (int k = 0; k < 16; k++) {
            float4 av = *(const float4*)&As[k][ty << 2];
            float a[4] = {av.x, av.y, av.z, av.w};
            float bb[8];
#pragma unroll
            for (int j = 0; j < 8; j++) bb[j] = Bs[k][tx + (j << 4)];
#pragma unroll
            for (int i = 0; i < 4; i++)
#pragma unroll
                for (int j = 0; j < 8; j++) acc[i][j] = fmaf(a[i], bb[j], acc[i][j]);
        }
        __syncthreads();
    }
#pragma unroll
    for (int j = 0; j < 8; j++) {
        float bj = bias[n0 + tx + (j << 4)];
#pragma unroll
        for (int i = 0; i < 4; i++)
            C[(m0 + (ty << 2) + i) * N + n0 + tx + (j << 4)] = acc[i][j] + bj;
    }
}

// ---------------------------------------------------------------------------
// prep_W: Wt[v,k] = split(W_joint[k,v]) into bf16 hi/lo planes
// ---------------------------------------------------------------------------
__global__ __launch_bounds__(256) void prep_w_kernel(const float* __restrict__ W) {
    int gid = blockIdx.x * 256 + threadIdx.x;       // 0 .. 524287
    int v = gid >> 9, k = gid & 511;
    float w = W[k * VOCAB + v];
    __nv_bfloat16 hi = __float2bfloat16_rn(w);
    __nv_bfloat16 lo = __float2bfloat16_rn(w - __bfloat162float(hi));
    g_wt_hi[gid] = hi;
    g_wt_lo[gid] = lo;
}

// ---------------------------------------------------------------------------
// prep_A: A[m,k] = tanh(enc_p[bt,k] + pred_p[b,u,k]) split into bf16 hi/lo
// ---------------------------------------------------------------------------
__global__ __launch_bounds__(256) void prep_a_kernel() {
    int gid = blockIdx.x * 256 + threadIdx.x;       // 0 .. 8388607
    int m  = gid >> 6;
    int k8 = (gid & 63) << 3;
    int bt = m >> 6;
    int b  = bt >> 8;
    int u  = m & 63;
    const float4* e = (const float4*)(g_enc_p + (size_t)bt * JDIM + k8);
    const float4* p = (const float4*)(g_pred_p + ((size_t)(b * UU + u)) * JDIM + k8);

    __nv_bfloat16 hi[8], lo[8];
#pragma unroll
    for (int q = 0; q < 2; q++) {
        float4 ev = e[q], pv = p[q];
        float v[4] = {ev.x + pv.x, ev.y + pv.y, ev.z + pv.z, ev.w + pv.w};
#pragma unroll
        for (int i = 0; i < 4; i++) {
            float t = tanh_f(v[i]);
            __nv_bfloat16 h = __float2bfloat16_rn(t);
            hi[q * 4 + i] = h;
            lo[q * 4 + i] = __float2bfloat16_rn(t - __bfloat162float(h));
        }
    }
    uint4 H, L;
    H.x = pack2(hi[0], hi[1]); H.y = pack2(hi[2], hi[3]);
    H.z = pack2(hi[4], hi[5]); H.w = pack2(hi[6], hi[7]);
    L.x = pack2(lo[0], lo[1]); L.y = pack2(lo[2], lo[3]);
    L.z = pack2(lo[4], lo[5]); L.w = pack2(lo[6], lo[7]);
    *(uint4*)(g_a_hi + (size_t)m * JDIM + k8) = H;
    *(uint4*)(g_a_lo + (size_t)m * JDIM + k8) = L;
}

// ---------------------------------------------------------------------------
// Joint GEMM via mma.sync (HMMA): C[131072,1024] = A_split @ Wt_split^T + bias
// BM=128, BN=256, BK=32, 256 threads (8 warps 2x4), warp tile 64x64.
// 3-stage cp.async pipeline. 3 bf16 passes: hh, lh, hl.
// ---------------------------------------------------------------------------
#define BM 128
#define BN 256
#define BK 32
#define NSTG 16                         // 512 / 32
#define ASTRIDE 80                      // 32 bf16 = 64B data, padded to 80B
#define A_PLANE (BM * ASTRIDE)          // 10240
#define B_PLANE (BN * ASTRIDE)          // 20480
#define STG_BYTES (2 * A_PLANE + 2 * B_PLANE)  // 61440
#define OFF_AHI 0
#define OFF_ALO A_PLANE
#define OFF_BHI (2 * A_PLANE)
#define OFF_BLO (2 * A_PLANE + B_PLANE)
#define JOINT_SMEM (3 * STG_BYTES + 1024)      // + bias

__device__ __forceinline__ void load_stage(uint32_t sbase, int k0, int m0, int n0, int tid) {
#pragma unroll
    for (int it = 0; it < 2; it++) {
        int c = tid + it * 256;
        int row = c >> 2, cq = c & 3;
        uint32_t d = sbase + row * ASTRIDE + cq * 16;
        size_t gof = (size_t)(m0 + row) * JDIM + k0 + cq * 8;
        CP16(d + OFF_AHI, g_a_hi + gof);
        CP16(d + OFF_ALO, g_a_lo + gof);
    }
#pragma unroll
    for (int it = 0; it < 4; it++) {
        int c = tid + it * 256;
        int row = c >> 2, cq = c & 3;
        uint32_t d = sbase + row * ASTRIDE + cq * 16;
        size_t gof = (size_t)(n0 + row) * JDIM + k0 + cq * 8;
        CP16(d + OFF_BHI, g_wt_hi + gof);
        CP16(d + OFF_BLO, g_wt_lo + gof);
    }
}

__global__ __launch_bounds__(256, 1) void joint_kernel(
    const float* __restrict__ bias, float* __restrict__ out)
{
    extern __shared__ char dsm[];
    const uint32_t sb = smem_u32(dsm);
    float* sbias = (float*)(dsm + 3 * STG_BYTES);

    const int tid = threadIdx.x;
    const int l   = tid & 31;
    const int w   = tid >> 5;
    const int mw  = w & 1;        // 0..1  -> 64-row slab
    const int nw  = w >> 1;       // 0..3  -> 64-col slab
    const int bid = blockIdx.x;
    const int n0  = (bid & 3) * BN;
    const int m0  = (bid >> 2) * BM;

    sbias[tid] = bias[n0 + tid];

    load_stage(sb + 0 * STG_BYTES, 0, m0, n0, tid);  CP_COMMIT();
    load_stage(sb + 1 * STG_BYTES, BK, m0, n0, tid); CP_COMMIT();

    float acc[4][8][4];
#pragma unroll
    for (int i = 0; i < 4; i++)
#pragma unroll
        for (int j = 0; j < 8; j++)
#pragma unroll
            for (int q = 0; q < 4; q++) acc[i][j][q] = 0.0f;

    // per-lane ldmatrix offsets (within a stage buffer)
    const uint32_t a_off = (uint32_t)((mw * 64 + (l & 15)) * ASTRIDE + (l >> 4) * 16);
    const uint32_t b_off = (uint32_t)((nw * 64 + ((l >> 4) << 3) + (l & 7)) * ASTRIDE
                                      + ((l >> 3) & 1) * 16);

    for (int s = 0; s < NSTG; s++) {
        asm volatile("cp.async.wait_group 1;" ::: "memory");
        __syncthreads();
        if (s + 2 < NSTG)
            load_stage(sb + ((s + 2) % 3) * STG_BYTES, (s + 2) * BK, m0, n0, tid);
        CP_COMMIT();

        const uint32_t stg = sb + (s % 3) * STG_BYTES;
#pragma unroll
        for (int kk = 0; kk < 2; kk++) {
            const uint32_t ka = kk * 32;   // 16 bf16 = 32 bytes
            uint32_t ah[4][4], al[4][4], bb[4][4];
#pragma unroll
            for (int mf = 0; mf < 4; mf++)
                LDSM4(ah[mf], stg + OFF_AHI + a_off + ka + mf * 16 * ASTRIDE);
#pragma unroll
            for (int np = 0; np < 4; np++)
                LDSM4(bb[np], stg + OFF_BHI + b_off + ka + np * 16 * ASTRIDE);
            // pass 1: A_hi * B_hi
#pragma unroll
            for (int mf = 0; mf < 4; mf++)
#pragma unroll
                for (int np = 0; np < 4; np++) {
                    MMA16816(acc[mf][np * 2 + 0], ah[mf], bb[np][0], bb[np][1]);
                    MMA16816(acc[mf][np * 2 + 1], ah[mf], bb[np][2], bb[np][3]);
                }
            // pass 2: A_lo * B_hi
#pragma unroll
            for (int mf = 0; mf < 4; mf++)
                LDSM4(al[mf], stg + OFF_ALO + a_off + ka + mf * 16 * ASTRIDE);
#pragma unroll
            for (int mf = 0; mf < 4; mf++)
#pragma unroll
                for (int np = 0; np < 4; np++) {
                    MMA16816(acc[mf][np * 2 + 0], al[mf], bb[np][0], bb[np][1]);
                    MMA16816(acc[mf][np * 2 + 1], al[mf], bb[np][2], bb[np][3]);
                }
            // pass 3: A_hi * B_lo (reuse bb regs)
#pragma unroll
            for (int np = 0; np < 4; np++)
                LDSM4(bb[np], stg + OFF_BLO + b_off + ka + np * 16 * ASTRIDE);
#pragma unroll
            for (int mf = 0; mf < 4; mf++)
#pragma unroll
                for (int np = 0; np < 4; np++) {
                    MMA16816(acc[mf][np * 2 + 0], ah[mf], bb[np][0], bb[np][1]);
                    MMA16816(acc[mf][np * 2 + 1], ah[mf], bb[np][2], bb[np][3]);
                }
        }
    }

    // epilogue: add bias, direct stores (float2 per c-frag half)
#pragma unroll
    for (int mf = 0; mf < 4; mf++) {
        const int r0 = m0 + mw * 64 + mf * 16 + (l >> 2);
#pragma unroll
        for (int nf = 0; nf < 8; nf++) {
            const int c  = n0 + nw * 64 + nf * 8 + ((l & 3) << 1);
            const float2 b2 = *(const float2*)&sbias[c - n0];
            float2 o0, o1;
            o0.x = acc[mf][nf][0] + b2.x;
            o0.y = acc[mf][nf][1] + b2.y;
            o1.x = acc[mf][nf][2] + b2.x;
            o1.y = acc[mf][nf][3] + b2.y;
            *(float2*)&out[(size_t)r0 * VOCAB + c]       = o0;
            *(float2*)&out[(size_t)(r0 + 8) * VOCAB + c] = o1;
        }
    }
}

// ---------------------------------------------------------------------------
extern "C" void kernel_launch(void* const* d_in, const int* in_sizes, int n_in,
                              void* d_out, int out_size)
{
    const float* enc_out  = (const float*)d_in[0];
    const float* pred_out = (const float*)d_in[1];
    const float* W_enc    = (const float*)d_in[2];
    const float* b_enc    = (const float*)d_in[3];
    const float* W_pred   = (const float*)d_in[4];
    const float* b_pred   = (const float*)d_in[5];
    const float* W_joint  = (const float*)d_in[6];
    const float* b_joint  = (const float*)d_in[7];
    float* out = (float*)d_out;

    static bool attr_done = false;
    if (!attr_done) {
        cudaFuncSetAttribute(joint_kernel, cudaFuncAttributeMaxDynamicSharedMemorySize, JOINT_SMEM);
        attr_done = true;
    }

    {
        dim3 grid(JDIM / 128, (BB * TT) / 64);
        proj_kernel<ENC_DIM, 0><<<grid, 256>>>(enc_out, W_enc, b_enc);
    }
    {
        dim3 grid(JDIM / 128, (BB * UU) / 64);
        proj_kernel<PRED_DIM, 1><<<grid, 256>>>(pred_out, W_pred, b_pred);
    }
    prep_w_kernel<<<(VOCAB * JDIM) / 256, 256>>>(W_joint);
    prep_a_kernel<<<((size_t)MROWS * JDIM / 8) / 256, 256>>>();
    // 1024 m-tiles x 4 n-tiles
    joint_kernel<<<(MROWS / BM) * (VOCAB / BN), 256, JOINT_SMEM>>>(b_joint, out);
}